// round 2
// baseline (speedup 1.0000x reference)
#include <cuda_runtime.h>

#define N_NODES 10000
#define N_EDGES 640000
#define D 128
#define N_LAYERS 4

// Scratch (static __device__ — no allocations allowed)
__device__ float g_bufA[N_NODES * D];   // layer input (after layer 0)
__device__ float g_bufB[N_NODES * D];   // hl = X@W + b
__device__ int   g_cnt[N_NODES];
__device__ int   g_cursor[N_NODES];
__device__ int   g_ptr[N_NODES + 1];
__device__ int   g_esrc[N_EDGES];

// ---------------------------------------------------------------------------
// CSR build (once per launch): dst-sorted edge list so aggregation is a pure
// gather (no fp32 atomics).
// ---------------------------------------------------------------------------
__global__ void zero_counts_kernel() {
    int i = blockIdx.x * blockDim.x + threadIdx.x;
    if (i < N_NODES) { g_cnt[i] = 0; g_cursor[i] = 0; }
}

__global__ void count_deg_kernel(const int* __restrict__ dst) {
    int e = blockIdx.x * blockDim.x + threadIdx.x;
    if (e < N_EDGES) atomicAdd(&g_cnt[dst[e]], 1);
}

// Single-block chunked exclusive scan over g_cnt -> g_ptr (10000 elements).
__global__ void scan_kernel() {
    __shared__ int warp_sums[32];
    __shared__ int carry_sh;
    int tid = threadIdx.x;                 // 1024 threads
    if (tid == 0) carry_sh = 0;
    __syncthreads();
    for (int base = 0; base < N_NODES; base += 1024) {
        int idx = base + tid;
        int v = (idx < N_NODES) ? g_cnt[idx] : 0;
        // inclusive warp scan
        int x = v;
        #pragma unroll
        for (int o = 1; o < 32; o <<= 1) {
            int y = __shfl_up_sync(0xFFFFFFFFu, x, o);
            if ((tid & 31) >= o) x += y;
        }
        if ((tid & 31) == 31) warp_sums[tid >> 5] = x;
        __syncthreads();
        if (tid < 32) {
            int s = warp_sums[tid];
            #pragma unroll
            for (int o = 1; o < 32; o <<= 1) {
                int y = __shfl_up_sync(0xFFFFFFFFu, s, o);
                if (tid >= o) s += y;
            }
            warp_sums[tid] = s;            // inclusive scan of warp sums
        }
        __syncthreads();
        int warp_off = (tid >= 32) ? warp_sums[(tid >> 5) - 1] : 0;
        int incl = x + warp_off;
        int excl = incl - v;
        int carry = carry_sh;
        if (idx < N_NODES) g_ptr[idx] = carry + excl;
        __syncthreads();
        if (tid == 1023) carry_sh = carry + incl;  // incl of tid 1023 = block total
        __syncthreads();
    }
    if (tid == 0) g_ptr[N_NODES] = carry_sh;
}

__global__ void fill_csr_kernel(const int* __restrict__ src,
                                const int* __restrict__ dst) {
    int e = blockIdx.x * blockDim.x + threadIdx.x;
    if (e < N_EDGES) {
        int d = dst[e];
        int pos = g_ptr[d] + atomicAdd(&g_cursor[d], 1);
        g_esrc[pos] = src[e];
    }
}

// ---------------------------------------------------------------------------
// GEMM: Y[N_NODES, D] = X @ W + b.  32 rows/block, 128 threads (thread = col).
// W chunk + X tile staged in shared; fp32 for precision across 4 layers.
// ---------------------------------------------------------------------------
#define GEMM_ROWS 32

__global__ void __launch_bounds__(128) gemm_bias_kernel(
    const float* __restrict__ ext_X, int use_ext,
    const float* __restrict__ W, const float* __restrict__ B) {
    __shared__ float sx[GEMM_ROWS][D];
    __shared__ float sw[32][D];
    const float* X = use_ext ? ext_X : g_bufA;
    int c = threadIdx.x;                   // 0..127 output column
    int row0 = blockIdx.x * GEMM_ROWS;

    #pragma unroll
    for (int i = 0; i < GEMM_ROWS; i++) {
        int r = row0 + i;
        sx[i][c] = (r < N_NODES) ? X[r * D + c] : 0.0f;
    }

    float acc[GEMM_ROWS];
    float bias = B[c];
    #pragma unroll
    for (int i = 0; i < GEMM_ROWS; i++) acc[i] = bias;

    for (int k0 = 0; k0 < D; k0 += 32) {
        __syncthreads();
        #pragma unroll
        for (int i = 0; i < 32; i++) sw[i][c] = W[(k0 + i) * D + c];
        __syncthreads();
        #pragma unroll 8
        for (int k = 0; k < 32; k++) {
            float w = sw[k][c];
            #pragma unroll
            for (int r = 0; r < GEMM_ROWS; r++)
                acc[r] = fmaf(sx[r][k0 + k], w, acc[r]);
        }
    }

    #pragma unroll
    for (int i = 0; i < GEMM_ROWS; i++) {
        int r = row0 + i;
        if (r < N_NODES) g_bufB[r * D + c] = acc[i];
    }
}

// ---------------------------------------------------------------------------
// Aggregate + self-loop + ReLU: one warp per node, float4 lanes (128B rows).
// Pure gather out of L2-resident g_bufB; 4-edge unroll for MLP.
// ---------------------------------------------------------------------------
__global__ void __launch_bounds__(256) agg_relu_kernel(float* __restrict__ ext_out,
                                                       int use_ext) {
    int gw = (blockIdx.x * blockDim.x + threadIdx.x) >> 5;
    if (gw >= N_NODES) return;
    int lane = threadIdx.x & 31;
    const float4* h4 = (const float4*)g_bufB;
    float4 a = h4[gw * 32 + lane];         // self-loop term (row = 32 float4)
    int s = g_ptr[gw], e = g_ptr[gw + 1];
    int i = s;
    for (; i + 4 <= e; i += 4) {
        int u0 = g_esrc[i], u1 = g_esrc[i + 1];
        int u2 = g_esrc[i + 2], u3 = g_esrc[i + 3];
        float4 v0 = h4[u0 * 32 + lane];
        float4 v1 = h4[u1 * 32 + lane];
        float4 v2 = h4[u2 * 32 + lane];
        float4 v3 = h4[u3 * 32 + lane];
        a.x += (v0.x + v1.x) + (v2.x + v3.x);
        a.y += (v0.y + v1.y) + (v2.y + v3.y);
        a.z += (v0.z + v1.z) + (v2.z + v3.z);
        a.w += (v0.w + v1.w) + (v2.w + v3.w);
    }
    for (; i < e; i++) {
        int u = g_esrc[i];
        float4 v = h4[u * 32 + lane];
        a.x += v.x; a.y += v.y; a.z += v.z; a.w += v.w;
    }
    a.x = fmaxf(a.x, 0.0f); a.y = fmaxf(a.y, 0.0f);
    a.z = fmaxf(a.z, 0.0f); a.w = fmaxf(a.w, 0.0f);
    float4* out4 = use_ext ? (float4*)ext_out : (float4*)g_bufA;
    out4[gw * 32 + lane] = a;
}

// ---------------------------------------------------------------------------
extern "C" void kernel_launch(void* const* d_in, const int* in_sizes, int n_in,
                              void* d_out, int out_size) {
    const float* node_feats = (const float*)d_in[0];
    const int*   src        = (const int*)d_in[1];
    const int*   dst        = (const int*)d_in[2];
    const float* Ws         = (const float*)d_in[3];
    const float* bs         = (const float*)d_in[4];
    float*       out        = (float*)d_out;

    // Build dst-CSR (per launch; deterministic work)
    zero_counts_kernel<<<(N_NODES + 255) / 256, 256>>>();
    count_deg_kernel<<<(N_EDGES + 255) / 256, 256>>>(dst);
    scan_kernel<<<1, 1024>>>();
    fill_csr_kernel<<<(N_EDGES + 255) / 256, 256>>>(src, dst);

    int gemm_grid = (N_NODES + GEMM_ROWS - 1) / GEMM_ROWS;      // 313
    int agg_grid  = (N_NODES * 32 + 255) / 256;                 // 1250

    for (int l = 0; l < N_LAYERS; l++) {
        gemm_bias_kernel<<<gemm_grid, 128>>>(node_feats, (l == 0) ? 1 : 0,
                                             Ws + (size_t)l * D * D,
                                             bs + (size_t)l * D);
        agg_relu_kernel<<<agg_grid, 256>>>(out, (l == N_LAYERS - 1) ? 1 : 0);
    }
}

// round 3
// speedup vs baseline: 1.2629x; 1.2629x over previous
#include <cuda_runtime.h>
#include <cuda_fp16.h>

#define N_NODES 10000
#define N_EDGES 640000
#define D 128
#define N_LAYERS 4
#define CAP 192            // max in-degree bucket (deg ~ Binom(640k,1e-4): mean 64, sd 8 -> 16 sigma margin)

// Scratch (static __device__ — no allocations allowed)
__device__ float  g_bufA[N_NODES * D];       // layer input (post-relu, fp32)
__device__ float  g_bufB[N_NODES * D];       // hl = X@W + b (fp32, self-loop + precision)
__device__ __half g_bufH[N_NODES * D];       // hl in fp16 (gather operand)
__device__ int    g_cursor[N_NODES];         // per-node degree counter
__device__ int    g_ell[N_NODES * CAP];      // padded per-dst source lists

// ---------------------------------------------------------------------------
// ELL build: zero cursors, then one atomic per edge into its dst bucket.
// No count pass, no scan, no ordering requirement.
// ---------------------------------------------------------------------------
__global__ void zero_cursor_kernel() {
    int i = blockIdx.x * blockDim.x + threadIdx.x;
    if (i < N_NODES) g_cursor[i] = 0;
}

__global__ void fill_ell_kernel(const int* __restrict__ src,
                                const int* __restrict__ dst) {
    int t = blockIdx.x * blockDim.x + threadIdx.x;
    int e0 = t * 4;
    if (e0 >= N_EDGES) return;                  // N_EDGES % 4 == 0
    int4 d4 = *(const int4*)&dst[e0];
    int4 s4 = *(const int4*)&src[e0];
    int p0 = atomicAdd(&g_cursor[d4.x], 1);
    int p1 = atomicAdd(&g_cursor[d4.y], 1);
    int p2 = atomicAdd(&g_cursor[d4.z], 1);
    int p3 = atomicAdd(&g_cursor[d4.w], 1);
    if (p0 < CAP) g_ell[d4.x * CAP + p0] = s4.x;
    if (p1 < CAP) g_ell[d4.y * CAP + p1] = s4.y;
    if (p2 < CAP) g_ell[d4.z * CAP + p2] = s4.z;
    if (p3 < CAP) g_ell[d4.w * CAP + p3] = s4.w;
}

// ---------------------------------------------------------------------------
// GEMM: Y = X @ W + b using packed dual-fp32 FMA (fma.rn.f32x2).
// Block tile: 32 rows x 128 cols, 128 threads.
// Thread: 4 row-pairs (8 rows) x 4 cols = 16 f32x2 accumulators.
// X tile stored TRANSPOSED in smem so one LDS.64 broadcast feeds a row-pair.
// Emits fp32 (g_bufB) + fp16 (g_bufH) copies of hl.
// ---------------------------------------------------------------------------
#define GR 32
#define RPAD (GR + 2)   // 34-float k-stride: 2-way write conflicts, 8B-aligned pairs

__device__ __forceinline__ float2 ffma2(float2 a, float2 b, float2 c) {
    unsigned long long ua = *reinterpret_cast<unsigned long long*>(&a);
    unsigned long long ub = *reinterpret_cast<unsigned long long*>(&b);
    unsigned long long uc = *reinterpret_cast<unsigned long long*>(&c);
    unsigned long long r;
    asm("fma.rn.f32x2 %0, %1, %2, %3;" : "=l"(r) : "l"(ua), "l"(ub), "l"(uc));
    return *reinterpret_cast<float2*>(&r);
}

__global__ void __launch_bounds__(128) gemm_bias_kernel(
    const float* __restrict__ ext_X, int use_ext,
    const float* __restrict__ W, const float* __restrict__ B) {
    __shared__ float sxt[D][RPAD];     // [k][r] transposed X tile
    __shared__ float sw_s[32][D];      // W chunk
    const float* X = use_ext ? ext_X : g_bufA;

    int tid = threadIdx.x;
    int cg = tid & 31, rg = tid >> 5;
    int c0 = cg * 4;
    int row0 = blockIdx.x * GR;

    // Load X tile transposed: thread owns k = tid, all 32 rows.
    #pragma unroll 4
    for (int r = 0; r < GR; r++) {
        int gr = row0 + r;
        sxt[tid][r] = (gr < N_NODES) ? X[gr * D + tid] : 0.0f;
    }

    float4 bias = *(const float4*)&B[c0];
    float2 acc[4][4];
    #pragma unroll
    for (int p = 0; p < 4; p++) {
        acc[p][0] = make_float2(bias.x, bias.x);
        acc[p][1] = make_float2(bias.y, bias.y);
        acc[p][2] = make_float2(bias.z, bias.z);
        acc[p][3] = make_float2(bias.w, bias.w);
    }

    for (int kc = 0; kc < D; kc += 32) {
        __syncthreads();
        #pragma unroll 4
        for (int i = 0; i < 32; i++)
            sw_s[i][tid] = W[(kc + i) * D + tid];
        __syncthreads();
        #pragma unroll
        for (int k = 0; k < 32; k++) {
            float4 w = *(float4*)&sw_s[k][c0];
            float2 w0 = make_float2(w.x, w.x);
            float2 w1 = make_float2(w.y, w.y);
            float2 w2 = make_float2(w.z, w.z);
            float2 w3 = make_float2(w.w, w.w);
            const float2* xr = (const float2*)&sxt[kc + k][rg * 8];
            #pragma unroll
            for (int p = 0; p < 4; p++) {
                float2 x2 = xr[p];                  // rows (rg*8+2p, +1), broadcast
                acc[p][0] = ffma2(x2, w0, acc[p][0]);
                acc[p][1] = ffma2(x2, w1, acc[p][1]);
                acc[p][2] = ffma2(x2, w2, acc[p][2]);
                acc[p][3] = ffma2(x2, w3, acc[p][3]);
            }
        }
    }

    #pragma unroll
    for (int p = 0; p < 4; p++) {
        int r0 = row0 + rg * 8 + 2 * p;
        float4 o0 = make_float4(acc[p][0].x, acc[p][1].x, acc[p][2].x, acc[p][3].x);
        float4 o1 = make_float4(acc[p][0].y, acc[p][1].y, acc[p][2].y, acc[p][3].y);
        if (r0 < N_NODES) {
            *(float4*)&g_bufB[r0 * D + c0] = o0;
            *(__half2*)&g_bufH[r0 * D + c0]     = __floats2half2_rn(o0.x, o0.y);
            *(__half2*)&g_bufH[r0 * D + c0 + 2] = __floats2half2_rn(o0.z, o0.w);
        }
        if (r0 + 1 < N_NODES) {
            *(float4*)&g_bufB[(r0 + 1) * D + c0] = o1;
            *(__half2*)&g_bufH[(r0 + 1) * D + c0]     = __floats2half2_rn(o1.x, o1.y);
            *(__half2*)&g_bufH[(r0 + 1) * D + c0 + 2] = __floats2half2_rn(o1.z, o1.w);
        }
    }
}

// ---------------------------------------------------------------------------
// Aggregate + self-loop + ReLU. One warp per node. Messages gathered as fp16
// (256B/row), self-loop read fp32, accumulation fp32, 4-edge unroll (int4 idx).
// ---------------------------------------------------------------------------
__device__ __forceinline__ void acc_h(float4& a, uint2 m) {
    float2 f0 = __half22float2(*reinterpret_cast<__half2*>(&m.x));
    float2 f1 = __half22float2(*reinterpret_cast<__half2*>(&m.y));
    a.x += f0.x; a.y += f0.y; a.z += f1.x; a.w += f1.y;
}

__global__ void __launch_bounds__(256) agg_relu_kernel(float* __restrict__ ext_out,
                                                       int use_ext) {
    int gw = (blockIdx.x * blockDim.x + threadIdx.x) >> 5;
    if (gw >= N_NODES) return;
    int lane = threadIdx.x & 31;

    const float4* s4 = (const float4*)g_bufB;
    float4 a = s4[gw * 32 + lane];                 // self-loop (fp32)

    int cnt = g_cursor[gw];
    if (cnt > CAP) cnt = CAP;
    const int* el = g_ell + gw * CAP;              // 16B-aligned (CAP % 4 == 0)
    const uint2* h2 = (const uint2*)g_bufH;        // 32 x 8B per row

    int j = 0;
    for (; j + 4 <= cnt; j += 4) {
        int4 e4 = *(const int4*)&el[j];
        uint2 m0 = h2[e4.x * 32 + lane];
        uint2 m1 = h2[e4.y * 32 + lane];
        uint2 m2 = h2[e4.z * 32 + lane];
        uint2 m3 = h2[e4.w * 32 + lane];
        acc_h(a, m0); acc_h(a, m1); acc_h(a, m2); acc_h(a, m3);
    }
    for (; j < cnt; j++) {
        uint2 m = h2[el[j] * 32 + lane];
        acc_h(a, m);
    }

    a.x = fmaxf(a.x, 0.0f); a.y = fmaxf(a.y, 0.0f);
    a.z = fmaxf(a.z, 0.0f); a.w = fmaxf(a.w, 0.0f);
    float4* out4 = use_ext ? (float4*)ext_out : (float4*)g_bufA;
    out4[gw * 32 + lane] = a;
}

// ---------------------------------------------------------------------------
extern "C" void kernel_launch(void* const* d_in, const int* in_sizes, int n_in,
                              void* d_out, int out_size) {
    const float* node_feats = (const float*)d_in[0];
    const int*   src        = (const int*)d_in[1];
    const int*   dst        = (const int*)d_in[2];
    const float* Ws         = (const float*)d_in[3];
    const float* bs         = (const float*)d_in[4];
    float*       out        = (float*)d_out;

    zero_cursor_kernel<<<(N_NODES + 255) / 256, 256>>>();
    fill_ell_kernel<<<(N_EDGES / 4 + 255) / 256, 256>>>(src, dst);

    int gemm_grid = (N_NODES + GR - 1) / GR;        // 313
    int agg_grid  = (N_NODES * 32 + 255) / 256;     // 1250

    for (int l = 0; l < N_LAYERS; l++) {
        gemm_bias_kernel<<<gemm_grid, 128>>>(node_feats, (l == 0) ? 1 : 0,
                                             Ws + (size_t)l * D * D,
                                             bs + (size_t)l * D);
        agg_relu_kernel<<<agg_grid, 256>>>(out, (l == N_LAYERS - 1) ? 1 : 0);
    }
}

// round 8
// speedup vs baseline: 1.3361x; 1.0579x over previous
#include <cuda_runtime.h>
#include <cuda_fp16.h>

#define N_NODES 10000
#define N_EDGES 640000
#define D 128
#define N_LAYERS 4
#define CAP 192            // max in-degree bucket (deg ~ Binom(640k,1e-4): mean 64, sd 8 -> 16 sigma margin)

#define H_SCALE   0.015625f   // 2^-6 applied when storing fp16 messages (exact)
#define H_UNSCALE 64.0f       // 2^6 applied when folding chunk sums into fp32

// Scratch (static __device__ — no allocations allowed)
__device__ float  g_bufA[N_NODES * D];       // layer input (post-relu, fp32)
__device__ float  g_bufB[N_NODES * D];       // hl = X@W + b (fp32, self-loop + precision)
__device__ __half g_bufH[N_NODES * D];       // hl * 2^-6 in fp16 (gather operand)
__device__ int    g_cursor[N_NODES];         // per-node degree counter
__device__ int    g_ell[N_NODES * CAP];      // padded per-dst source lists

// ---------------------------------------------------------------------------
// ELL build
// ---------------------------------------------------------------------------
__global__ void zero_cursor_kernel() {
    int i = blockIdx.x * blockDim.x + threadIdx.x;
    if (i < N_NODES) g_cursor[i] = 0;
}

__global__ void fill_ell_kernel(const int* __restrict__ src,
                                const int* __restrict__ dst) {
    int t = blockIdx.x * blockDim.x + threadIdx.x;
    int e0 = t * 4;
    if (e0 >= N_EDGES) return;                  // N_EDGES % 4 == 0
    int4 d4 = *(const int4*)&dst[e0];
    int4 s4 = *(const int4*)&src[e0];
    int p0 = atomicAdd(&g_cursor[d4.x], 1);
    int p1 = atomicAdd(&g_cursor[d4.y], 1);
    int p2 = atomicAdd(&g_cursor[d4.z], 1);
    int p3 = atomicAdd(&g_cursor[d4.w], 1);
    if (p0 < CAP) g_ell[d4.x * CAP + p0] = s4.x;
    if (p1 < CAP) g_ell[d4.y * CAP + p1] = s4.y;
    if (p2 < CAP) g_ell[d4.z * CAP + p2] = s4.z;
    if (p3 < CAP) g_ell[d4.w * CAP + p3] = s4.w;
}

// ---------------------------------------------------------------------------
// GEMM: Y = X @ W + b using packed dual-fp32 FMA (fma.rn.f32x2).
// ---------------------------------------------------------------------------
#define GR 32
#define RPAD (GR + 2)

__device__ __forceinline__ float2 ffma2(float2 a, float2 b, float2 c) {
    unsigned long long ua = *reinterpret_cast<unsigned long long*>(&a);
    unsigned long long ub = *reinterpret_cast<unsigned long long*>(&b);
    unsigned long long uc = *reinterpret_cast<unsigned long long*>(&c);
    unsigned long long r;
    asm("fma.rn.f32x2 %0, %1, %2, %3;" : "=l"(r) : "l"(ua), "l"(ub), "l"(uc));
    return *reinterpret_cast<float2*>(&r);
}

__global__ void __launch_bounds__(128) gemm_bias_kernel(
    const float* __restrict__ ext_X, int use_ext,
    const float* __restrict__ W, const float* __restrict__ B) {
    __shared__ float sxt[D][RPAD];     // [k][r] transposed X tile
    __shared__ float sw_s[32][D];      // W chunk
    const float* X = use_ext ? ext_X : g_bufA;

    int tid = threadIdx.x;
    int cg = tid & 31, rg = tid >> 5;
    int c0 = cg * 4;
    int row0 = blockIdx.x * GR;

    #pragma unroll 4
    for (int r = 0; r < GR; r++) {
        int gr = row0 + r;
        sxt[tid][r] = (gr < N_NODES) ? X[gr * D + tid] : 0.0f;
    }

    float4 bias = *(const float4*)&B[c0];
    float2 acc[4][4];
    #pragma unroll
    for (int p = 0; p < 4; p++) {
        acc[p][0] = make_float2(bias.x, bias.x);
        acc[p][1] = make_float2(bias.y, bias.y);
        acc[p][2] = make_float2(bias.z, bias.z);
        acc[p][3] = make_float2(bias.w, bias.w);
    }

    for (int kc = 0; kc < D; kc += 32) {
        __syncthreads();
        #pragma unroll 4
        for (int i = 0; i < 32; i++)
            sw_s[i][tid] = W[(kc + i) * D + tid];
        __syncthreads();
        #pragma unroll
        for (int k = 0; k < 32; k++) {
            float4 w = *(float4*)&sw_s[k][c0];
            float2 w0 = make_float2(w.x, w.x);
            float2 w1 = make_float2(w.y, w.y);
            float2 w2 = make_float2(w.z, w.z);
            float2 w3 = make_float2(w.w, w.w);
            const float2* xr = (const float2*)&sxt[kc + k][rg * 8];
            #pragma unroll
            for (int p = 0; p < 4; p++) {
                float2 x2 = xr[p];
                acc[p][0] = ffma2(x2, w0, acc[p][0]);
                acc[p][1] = ffma2(x2, w1, acc[p][1]);
                acc[p][2] = ffma2(x2, w2, acc[p][2]);
                acc[p][3] = ffma2(x2, w3, acc[p][3]);
            }
        }
    }

    #pragma unroll
    for (int p = 0; p < 4; p++) {
        int r0 = row0 + rg * 8 + 2 * p;
        float4 o0 = make_float4(acc[p][0].x, acc[p][1].x, acc[p][2].x, acc[p][3].x);
        float4 o1 = make_float4(acc[p][0].y, acc[p][1].y, acc[p][2].y, acc[p][3].y);
        if (r0 < N_NODES) {
            *(float4*)&g_bufB[r0 * D + c0] = o0;
            *(__half2*)&g_bufH[r0 * D + c0]     = __floats2half2_rn(o0.x * H_SCALE, o0.y * H_SCALE);
            *(__half2*)&g_bufH[r0 * D + c0 + 2] = __floats2half2_rn(o0.z * H_SCALE, o0.w * H_SCALE);
        }
        if (r0 + 1 < N_NODES) {
            *(float4*)&g_bufB[(r0 + 1) * D + c0] = o1;
            *(__half2*)&g_bufH[(r0 + 1) * D + c0]     = __floats2half2_rn(o1.x * H_SCALE, o1.y * H_SCALE);
            *(__half2*)&g_bufH[(r0 + 1) * D + c0 + 2] = __floats2half2_rn(o1.z * H_SCALE, o1.w * H_SCALE);
        }
    }
}

// ---------------------------------------------------------------------------
// Aggregate + self-loop + ReLU. One warp per node. 8-edge chunks accumulated
// in fp16 via pairwise HADD2 trees on PRE-SCALED (x 2^-6) messages — partial
// sums bounded ~8k << 65504, no overflow. Chunk sum unscaled (x 2^6) into the
// fp32 accumulator (FMA). Per-edge warp-instr count ~4.
// ---------------------------------------------------------------------------
__device__ __forceinline__ __half2 H2(unsigned int u) {
    return *reinterpret_cast<__half2*>(&u);
}

__global__ void __launch_bounds__(256) agg_relu_kernel(float* __restrict__ ext_out,
                                                       int use_ext) {
    int gw = (blockIdx.x * blockDim.x + threadIdx.x) >> 5;
    if (gw >= N_NODES) return;
    int lane = threadIdx.x & 31;

    const float4* s4 = (const float4*)g_bufB;
    float4 a = s4[gw * 32 + lane];                 // self-loop (fp32, unscaled)

    int cnt = g_cursor[gw];
    if (cnt > CAP) cnt = CAP;
    const int* el = g_ell + gw * CAP;
    const uint2* h2 = ((const uint2*)g_bufH) + lane;   // row stride = 32 uint2

    int j = 0;
    for (; j + 8 <= cnt; j += 8) {
        int4 eA = *(const int4*)&el[j];
        int4 eB = *(const int4*)&el[j + 4];
        uint2 m0 = h2[eA.x * 32];
        uint2 m1 = h2[eA.y * 32];
        uint2 m2 = h2[eA.z * 32];
        uint2 m3 = h2[eA.w * 32];
        uint2 m4 = h2[eB.x * 32];
        uint2 m5 = h2[eB.y * 32];
        uint2 m6 = h2[eB.z * 32];
        uint2 m7 = h2[eB.w * 32];
        // low half2 (features 4*lane .. +1)
        __half2 tL0 = __hadd2(H2(m0.x), H2(m1.x));
        __half2 tL1 = __hadd2(H2(m2.x), H2(m3.x));
        __half2 tL2 = __hadd2(H2(m4.x), H2(m5.x));
        __half2 tL3 = __hadd2(H2(m6.x), H2(m7.x));
        __half2 sL  = __hadd2(__hadd2(tL0, tL1), __hadd2(tL2, tL3));
        // high half2 (features 4*lane+2 .. +3)
        __half2 tH0 = __hadd2(H2(m0.y), H2(m1.y));
        __half2 tH1 = __hadd2(H2(m2.y), H2(m3.y));
        __half2 tH2 = __hadd2(H2(m4.y), H2(m5.y));
        __half2 tH3 = __hadd2(H2(m6.y), H2(m7.y));
        __half2 sH  = __hadd2(__hadd2(tH0, tH1), __hadd2(tH2, tH3));
        float2 fL = __half22float2(sL);
        float2 fH = __half22float2(sH);
        a.x = fmaf(fL.x, H_UNSCALE, a.x);
        a.y = fmaf(fL.y, H_UNSCALE, a.y);
        a.z = fmaf(fH.x, H_UNSCALE, a.z);
        a.w = fmaf(fH.y, H_UNSCALE, a.w);
    }
    // tail (<8 edges): scalar fp32 path (unscale each message)
    for (; j < cnt; j++) {
        uint2 m = h2[el[j] * 32];
        float2 fL = __half22float2(H2(m.x));
        float2 fH = __half22float2(H2(m.y));
        a.x = fmaf(fL.x, H_UNSCALE, a.x);
        a.y = fmaf(fL.y, H_UNSCALE, a.y);
        a.z = fmaf(fH.x, H_UNSCALE, a.z);
        a.w = fmaf(fH.y, H_UNSCALE, a.w);
    }

    a.x = fmaxf(a.x, 0.0f); a.y = fmaxf(a.y, 0.0f);
    a.z = fmaxf(a.z, 0.0f); a.w = fmaxf(a.w, 0.0f);
    float4* out4 = use_ext ? (float4*)ext_out : (float4*)g_bufA;
    out4[gw * 32 + lane] = a;
}

// ---------------------------------------------------------------------------
extern "C" void kernel_launch(void* const* d_in, const int* in_sizes, int n_in,
                              void* d_out, int out_size) {
    const float* node_feats = (const float*)d_in[0];
    const int*   src        = (const int*)d_in[1];
    const int*   dst        = (const int*)d_in[2];
    const float* Ws         = (const float*)d_in[3];
    const float* bs         = (const float*)d_in[4];
    float*       out        = (float*)d_out;

    zero_cursor_kernel<<<(N_NODES + 255) / 256, 256>>>();
    fill_ell_kernel<<<(N_EDGES / 4 + 255) / 256, 256>>>(src, dst);

    int gemm_grid = (N_NODES + GR - 1) / GR;        // 313
    int agg_grid  = (N_NODES * 32 + 255) / 256;     // 1250

    for (int l = 0; l < N_LAYERS; l++) {
        gemm_bias_kernel<<<gemm_grid, 128>>>(node_feats, (l == 0) ? 1 : 0,
                                             Ws + (size_t)l * D * D,
                                             bs + (size_t)l * D);
        agg_relu_kernel<<<agg_grid, 256>>>(out, (l == N_LAYERS - 1) ? 1 : 0);
    }
}

// round 9
// speedup vs baseline: 1.3965x; 1.0452x over previous
#include <cuda_runtime.h>
#include <cuda_fp16.h>

#define N_NODES 10000
#define N_EDGES 640000
#define D 128
#define N_LAYERS 4
#define CAP 192            // max in-degree bucket (deg ~ Binom(640k,1e-4): mean 64, sd 8 -> 16 sigma margin)

#define H_SCALE   0.015625f   // 2^-6 applied when storing fp16 messages (exact)
#define H_UNSCALE 64.0f       // 2^6 applied when folding chunk sums into fp32

// Scratch (static __device__ — no allocations allowed)
__device__ float  g_bufA[N_NODES * D];       // layer input (post-relu, fp32)
__device__ float  g_bufB[N_NODES * D];       // hl = X@W + b (fp32, self-loop + precision)
__device__ __half g_bufH[N_NODES * D];       // hl * 2^-6 in fp16 (gather operand)
__device__ int    g_cursor[N_NODES];         // per-node degree counter
__device__ int    g_ell[N_NODES * CAP];      // padded per-dst source lists

// ---------------------------------------------------------------------------
// ELL build
// ---------------------------------------------------------------------------
__global__ void zero_cursor_kernel() {
    int i = blockIdx.x * blockDim.x + threadIdx.x;
    if (i < N_NODES) g_cursor[i] = 0;
}

// 8 edges per thread: 8 independent atomic->store chains in flight.
__global__ void fill_ell_kernel(const int* __restrict__ src,
                                const int* __restrict__ dst) {
    int t = blockIdx.x * blockDim.x + threadIdx.x;
    int e0 = t * 8;
    if (e0 >= N_EDGES) return;                  // N_EDGES % 8 == 0
    int4 dA = *(const int4*)&dst[e0];
    int4 dB = *(const int4*)&dst[e0 + 4];
    int4 sA = *(const int4*)&src[e0];
    int4 sB = *(const int4*)&src[e0 + 4];
    int p0 = atomicAdd(&g_cursor[dA.x], 1);
    int p1 = atomicAdd(&g_cursor[dA.y], 1);
    int p2 = atomicAdd(&g_cursor[dA.z], 1);
    int p3 = atomicAdd(&g_cursor[dA.w], 1);
    int p4 = atomicAdd(&g_cursor[dB.x], 1);
    int p5 = atomicAdd(&g_cursor[dB.y], 1);
    int p6 = atomicAdd(&g_cursor[dB.z], 1);
    int p7 = atomicAdd(&g_cursor[dB.w], 1);
    if (p0 < CAP) g_ell[dA.x * CAP + p0] = sA.x;
    if (p1 < CAP) g_ell[dA.y * CAP + p1] = sA.y;
    if (p2 < CAP) g_ell[dA.z * CAP + p2] = sA.z;
    if (p3 < CAP) g_ell[dA.w * CAP + p3] = sA.w;
    if (p4 < CAP) g_ell[dB.x * CAP + p4] = sB.x;
    if (p5 < CAP) g_ell[dB.y * CAP + p5] = sB.y;
    if (p6 < CAP) g_ell[dB.z * CAP + p6] = sB.z;
    if (p7 < CAP) g_ell[dB.w * CAP + p7] = sB.w;
}

// ---------------------------------------------------------------------------
// GEMM: Y = X @ W + b using packed dual-fp32 FMA (fma.rn.f32x2).
// ---------------------------------------------------------------------------
#define GR 32
#define RPAD (GR + 2)

__device__ __forceinline__ float2 ffma2(float2 a, float2 b, float2 c) {
    unsigned long long ua = *reinterpret_cast<unsigned long long*>(&a);
    unsigned long long ub = *reinterpret_cast<unsigned long long*>(&b);
    unsigned long long uc = *reinterpret_cast<unsigned long long*>(&c);
    unsigned long long r;
    asm("fma.rn.f32x2 %0, %1, %2, %3;" : "=l"(r) : "l"(ua), "l"(ub), "l"(uc));
    return *reinterpret_cast<float2*>(&r);
}

__global__ void __launch_bounds__(128) gemm_bias_kernel(
    const float* __restrict__ ext_X, int use_ext,
    const float* __restrict__ W, const float* __restrict__ B) {
    __shared__ float sxt[D][RPAD];     // [k][r] transposed X tile
    __shared__ float sw_s[32][D];      // W chunk
    const float* X = use_ext ? ext_X : g_bufA;

    int tid = threadIdx.x;
    int cg = tid & 31, rg = tid >> 5;
    int c0 = cg * 4;
    int row0 = blockIdx.x * GR;

    #pragma unroll 4
    for (int r = 0; r < GR; r++) {
        int gr = row0 + r;
        sxt[tid][r] = (gr < N_NODES) ? X[gr * D + tid] : 0.0f;
    }

    float4 bias = *(const float4*)&B[c0];
    float2 acc[4][4];
    #pragma unroll
    for (int p = 0; p < 4; p++) {
        acc[p][0] = make_float2(bias.x, bias.x);
        acc[p][1] = make_float2(bias.y, bias.y);
        acc[p][2] = make_float2(bias.z, bias.z);
        acc[p][3] = make_float2(bias.w, bias.w);
    }

    for (int kc = 0; kc < D; kc += 32) {
        __syncthreads();
        #pragma unroll 4
        for (int i = 0; i < 32; i++)
            sw_s[i][tid] = W[(kc + i) * D + tid];
        __syncthreads();
        #pragma unroll
        for (int k = 0; k < 32; k++) {
            float4 w = *(float4*)&sw_s[k][c0];
            float2 w0 = make_float2(w.x, w.x);
            float2 w1 = make_float2(w.y, w.y);
            float2 w2 = make_float2(w.z, w.z);
            float2 w3 = make_float2(w.w, w.w);
            const float2* xr = (const float2*)&sxt[kc + k][rg * 8];
            #pragma unroll
            for (int p = 0; p < 4; p++) {
                float2 x2 = xr[p];
                acc[p][0] = ffma2(x2, w0, acc[p][0]);
                acc[p][1] = ffma2(x2, w1, acc[p][1]);
                acc[p][2] = ffma2(x2, w2, acc[p][2]);
                acc[p][3] = ffma2(x2, w3, acc[p][3]);
            }
        }
    }

    #pragma unroll
    for (int p = 0; p < 4; p++) {
        int r0 = row0 + rg * 8 + 2 * p;
        float4 o0 = make_float4(acc[p][0].x, acc[p][1].x, acc[p][2].x, acc[p][3].x);
        float4 o1 = make_float4(acc[p][0].y, acc[p][1].y, acc[p][2].y, acc[p][3].y);
        if (r0 < N_NODES) {
            *(float4*)&g_bufB[r0 * D + c0] = o0;
            *(__half2*)&g_bufH[r0 * D + c0]     = __floats2half2_rn(o0.x * H_SCALE, o0.y * H_SCALE);
            *(__half2*)&g_bufH[r0 * D + c0 + 2] = __floats2half2_rn(o0.z * H_SCALE, o0.w * H_SCALE);
        }
        if (r0 + 1 < N_NODES) {
            *(float4*)&g_bufB[(r0 + 1) * D + c0] = o1;
            *(__half2*)&g_bufH[(r0 + 1) * D + c0]     = __floats2half2_rn(o1.x * H_SCALE, o1.y * H_SCALE);
            *(__half2*)&g_bufH[(r0 + 1) * D + c0 + 2] = __floats2half2_rn(o1.z * H_SCALE, o1.w * H_SCALE);
        }
    }
}

// ---------------------------------------------------------------------------
// Aggregate + self-loop + ReLU. One warp per node. 16-edge chunks: all 16
// gathers + 4 int4 index loads issued up front (MLP=16/warp), then two
// independent 8-wide HADD2 trees on pre-scaled (x 2^-6) fp16 messages, each
// folded into the fp32 accumulator (numerics identical per 8-chunk to R8).
// ---------------------------------------------------------------------------
__device__ __forceinline__ __half2 H2(unsigned int u) {
    return *reinterpret_cast<__half2*>(&u);
}

// 8-message fp16 tree -> fold into fp32 acc with unscale
__device__ __forceinline__ void tree8(float4& a,
    uint2 m0, uint2 m1, uint2 m2, uint2 m3,
    uint2 m4, uint2 m5, uint2 m6, uint2 m7) {
    __half2 tL0 = __hadd2(H2(m0.x), H2(m1.x));
    __half2 tL1 = __hadd2(H2(m2.x), H2(m3.x));
    __half2 tL2 = __hadd2(H2(m4.x), H2(m5.x));
    __half2 tL3 = __hadd2(H2(m6.x), H2(m7.x));
    __half2 sL  = __hadd2(__hadd2(tL0, tL1), __hadd2(tL2, tL3));
    __half2 tH0 = __hadd2(H2(m0.y), H2(m1.y));
    __half2 tH1 = __hadd2(H2(m2.y), H2(m3.y));
    __half2 tH2 = __hadd2(H2(m4.y), H2(m5.y));
    __half2 tH3 = __hadd2(H2(m6.y), H2(m7.y));
    __half2 sH  = __hadd2(__hadd2(tH0, tH1), __hadd2(tH2, tH3));
    float2 fL = __half22float2(sL);
    float2 fH = __half22float2(sH);
    a.x = fmaf(fL.x, H_UNSCALE, a.x);
    a.y = fmaf(fL.y, H_UNSCALE, a.y);
    a.z = fmaf(fH.x, H_UNSCALE, a.z);
    a.w = fmaf(fH.y, H_UNSCALE, a.w);
}

__global__ void __launch_bounds__(256) agg_relu_kernel(float* __restrict__ ext_out,
                                                       int use_ext) {
    int gw = (blockIdx.x * blockDim.x + threadIdx.x) >> 5;
    if (gw >= N_NODES) return;
    int lane = threadIdx.x & 31;

    const float4* s4 = (const float4*)g_bufB;
    float4 a = s4[gw * 32 + lane];                 // self-loop (fp32, unscaled)

    int cnt = g_cursor[gw];
    if (cnt > CAP) cnt = CAP;
    const int* el = g_ell + gw * CAP;
    const uint2* h2 = ((const uint2*)g_bufH) + lane;   // row stride = 32 uint2

    int j = 0;
    for (; j + 16 <= cnt; j += 16) {
        int4 eA = *(const int4*)&el[j];
        int4 eB = *(const int4*)&el[j + 4];
        int4 eC = *(const int4*)&el[j + 8];
        int4 eD = *(const int4*)&el[j + 12];
        uint2 m0 = h2[eA.x * 32];
        uint2 m1 = h2[eA.y * 32];
        uint2 m2 = h2[eA.z * 32];
        uint2 m3 = h2[eA.w * 32];
        uint2 m4 = h2[eB.x * 32];
        uint2 m5 = h2[eB.y * 32];
        uint2 m6 = h2[eB.z * 32];
        uint2 m7 = h2[eB.w * 32];
        uint2 n0 = h2[eC.x * 32];
        uint2 n1 = h2[eC.y * 32];
        uint2 n2 = h2[eC.z * 32];
        uint2 n3 = h2[eC.w * 32];
        uint2 n4 = h2[eD.x * 32];
        uint2 n5 = h2[eD.y * 32];
        uint2 n6 = h2[eD.z * 32];
        uint2 n7 = h2[eD.w * 32];
        tree8(a, m0, m1, m2, m3, m4, m5, m6, m7);
        tree8(a, n0, n1, n2, n3, n4, n5, n6, n7);
    }
    for (; j + 8 <= cnt; j += 8) {
        int4 eA = *(const int4*)&el[j];
        int4 eB = *(const int4*)&el[j + 4];
        uint2 m0 = h2[eA.x * 32];
        uint2 m1 = h2[eA.y * 32];
        uint2 m2 = h2[eA.z * 32];
        uint2 m3 = h2[eA.w * 32];
        uint2 m4 = h2[eB.x * 32];
        uint2 m5 = h2[eB.y * 32];
        uint2 m6 = h2[eB.z * 32];
        uint2 m7 = h2[eB.w * 32];
        tree8(a, m0, m1, m2, m3, m4, m5, m6, m7);
    }
    // tail (<8 edges): scalar fp32 path (unscale each message)
    for (; j < cnt; j++) {
        uint2 m = h2[el[j] * 32];
        float2 fL = __half22float2(H2(m.x));
        float2 fH = __half22float2(H2(m.y));
        a.x = fmaf(fL.x, H_UNSCALE, a.x);
        a.y = fmaf(fL.y, H_UNSCALE, a.y);
        a.z = fmaf(fH.x, H_UNSCALE, a.z);
        a.w = fmaf(fH.y, H_UNSCALE, a.w);
    }

    a.x = fmaxf(a.x, 0.0f); a.y = fmaxf(a.y, 0.0f);
    a.z = fmaxf(a.z, 0.0f); a.w = fmaxf(a.w, 0.0f);
    float4* out4 = use_ext ? (float4*)ext_out : (float4*)g_bufA;
    out4[gw * 32 + lane] = a;
}

// ---------------------------------------------------------------------------
extern "C" void kernel_launch(void* const* d_in, const int* in_sizes, int n_in,
                              void* d_out, int out_size) {
    const float* node_feats = (const float*)d_in[0];
    const int*   src        = (const int*)d_in[1];
    const int*   dst        = (const int*)d_in[2];
    const float* Ws         = (const float*)d_in[3];
    const float* bs         = (const float*)d_in[4];
    float*       out        = (float*)d_out;

    zero_cursor_kernel<<<(N_NODES + 255) / 256, 256>>>();
    fill_ell_kernel<<<(N_EDGES / 8 + 255) / 256, 256>>>(src, dst);

    int gemm_grid = (N_NODES + GR - 1) / GR;        // 313
    int agg_grid  = (N_NODES * 32 + 255) / 256;     // 1250

    for (int l = 0; l < N_LAYERS; l++) {
        gemm_bias_kernel<<<gemm_grid, 128>>>(node_feats, (l == 0) ? 1 : 0,
                                             Ws + (size_t)l * D * D,
                                             bs + (size_t)l * D);
        agg_relu_kernel<<<agg_grid, 256>>>(out, (l == N_LAYERS - 1) ? 1 : 0);
    }
}